// round 17
// baseline (speedup 1.0000x reference)
#include <cuda_runtime.h>
#include <cuda_fp16.h>
#include <cstdint>

#define NB 4
#define H  512
#define HP (H + 2)         // haloed column length (g in [-1, 512])
#define W  360
#define D  512
#define HW (H*W)           // 184320
#define DD (D*D)           // 262144
#define WLEN 48
#define NSTG 16            // ring buffers (groups of 4, 3 groups live max)
#define QW 90              // angles per backproj CTA (4-way angle split)
#define KSL 8              // filter K-slices
#define KCH (H / KSL)      // 64 k per slice

// ---- device scratch (no allocations allowed) ----
__device__ float4 g_fpart[KSL][W * H];  // fp32 filter partials per K-slice
__device__ uint4  g_pkt[W * HP];        // fp16 val+delta, haloed: {v01, v23, d01, d23}
__device__ uint2  g_parth[4][DD];       // fp16-packed backproj partials {h2(b0,b1), h2(b2,b3)}

// ---- packed f32x2 helpers (FFMA2) ----
__device__ __forceinline__ unsigned long long pk2(float a, float b) {
    unsigned long long r;
    asm("mov.b64 %0, {%1, %2};" : "=l"(r) : "f"(a), "f"(b));
    return r;
}
__device__ __forceinline__ void upk2(unsigned long long v, float &a, float &b) {
    asm("mov.b64 {%0, %1}, %2;" : "=f"(a), "=f"(b) : "l"(v));
}
__device__ __forceinline__ void ffma2(unsigned long long &acc,
                                      unsigned long long a, unsigned long long b) {
    asm("fma.rn.f32x2 %0, %1, %2, %0;" : "+l"(acc) : "l"(a), "l"(b));
}
__device__ __forceinline__ __half2 u2h(unsigned u) { return *(__half2*)&u; }

// ============================================================
// Filter (K-split): C_z[i,c] = sum_{j in slice z} hG[(j-i-257)&511] * X[j,c]
// BM=64, BN=64, K=64/slice, grid (8,23,KSL)=1472 CTAs.
// ============================================================
__global__ __launch_bounds__(256) void filter_kernel(const float* __restrict__ x,
                                                     const float* __restrict__ hG) {
    __shared__ float hs[512];
    __shared__ float Fs[16][64];
    __shared__ float Xs[16][64];

    int tid = threadIdx.x;
    hs[tid]       = hG[tid];
    hs[tid + 256] = hG[tid + 256];

    int tx = tid & 15;
    int ty = tid >> 4;
    int iblk = blockIdx.x * 64;
    int cblk = blockIdx.y * 64;
    int kbase = blockIdx.z * KCH;

    int lk  = ty;
    int lo4 = tx * 4;

    int wst = (cblk + lo4) >> 2;
    bool okw = (wst < W);
    const float* Xg = x + wst;

    int jb0 = -(iblk + lo4) - 257;

    __syncthreads();

    float4 fv;
    {
        int b = jb0 + kbase + lk;
        fv.x = hs[(b    ) & 511];
        fv.y = hs[(b - 1) & 511];
        fv.z = hs[(b - 2) & 511];
        fv.w = hs[(b - 3) & 511];
    }
    float xv0 = 0.f, xv1 = 0.f, xv2 = 0.f, xv3 = 0.f;
    if (okw) {
        xv0 = Xg[0 * HW + (kbase + lk) * W];
        xv1 = Xg[1 * HW + (kbase + lk) * W];
        xv2 = Xg[2 * HW + (kbase + lk) * W];
        xv3 = Xg[3 * HW + (kbase + lk) * W];
    }

    unsigned long long acc2[4][2] = {};

    for (int kk = 0; kk < KCH; kk += 16) {
        __syncthreads();
        *(float4*)&Fs[lk][lo4] = fv;
        Xs[lk][lo4 + 0] = xv0;
        Xs[lk][lo4 + 1] = xv1;
        Xs[lk][lo4 + 2] = xv2;
        Xs[lk][lo4 + 3] = xv3;
        __syncthreads();

        int kn = kk + 16;
        if (kn < KCH) {
            int b = jb0 + kbase + kn + lk;
            fv.x = hs[(b    ) & 511];
            fv.y = hs[(b - 1) & 511];
            fv.z = hs[(b - 2) & 511];
            fv.w = hs[(b - 3) & 511];
            if (okw) {
                xv0 = Xg[0 * HW + (kbase + kn + lk) * W];
                xv1 = Xg[1 * HW + (kbase + kn + lk) * W];
                xv2 = Xg[2 * HW + (kbase + kn + lk) * W];
                xv3 = Xg[3 * HW + (kbase + kn + lk) * W];
            }
        }

        #pragma unroll
        for (int k = 0; k < 16; ++k) {
            float4 a  = *(const float4*)&Fs[k][tx * 4];
            float4 b4 = *(const float4*)&Xs[k][ty * 4];
            unsigned long long b01 = pk2(b4.x, b4.y);
            unsigned long long b23 = pk2(b4.z, b4.w);
            unsigned long long ax = pk2(a.x, a.x);
            unsigned long long ay = pk2(a.y, a.y);
            unsigned long long az = pk2(a.z, a.z);
            unsigned long long aw = pk2(a.w, a.w);
            ffma2(acc2[0][0], ax, b01);  ffma2(acc2[0][1], ax, b23);
            ffma2(acc2[1][0], ay, b01);  ffma2(acc2[1][1], ay, b23);
            ffma2(acc2[2][0], az, b01);  ffma2(acc2[2][1], az, b23);
            ffma2(acc2[3][0], aw, b01);  ffma2(acc2[3][1], aw, b23);
        }
    }

    int wout = (cblk >> 2) + ty;
    if (wout < W) {
        float4* pout = g_fpart[blockIdx.z];
        #pragma unroll
        for (int ii = 0; ii < 4; ++ii) {
            float b0, b1, b2, b3;
            upk2(acc2[ii][0], b0, b1);
            upk2(acc2[ii][1], b2, b3);
            pout[wout * H + iblk + tx * 4 + ii] = make_float4(b0, b1, b2, b3);
        }
    }
}

// ============================================================
// Reduce: pairwise-sum 8 K-slice partials; emit haloed fp16
// val+delta table (same boundary encoding as before).
// ============================================================
__device__ __forceinline__ float4 sum8(int i) {
    float4 r;
    float4 a0 = g_fpart[0][i], a1 = g_fpart[1][i];
    float4 a2 = g_fpart[2][i], a3 = g_fpart[3][i];
    float4 a4 = g_fpart[4][i], a5 = g_fpart[5][i];
    float4 a6 = g_fpart[6][i], a7 = g_fpart[7][i];
    r.x = ((a0.x + a1.x) + (a2.x + a3.x)) + ((a4.x + a5.x) + (a6.x + a7.x));
    r.y = ((a0.y + a1.y) + (a2.y + a3.y)) + ((a4.y + a5.y) + (a6.y + a7.y));
    r.z = ((a0.z + a1.z) + (a2.z + a3.z)) + ((a4.z + a5.z) + (a6.z + a7.z));
    r.w = ((a0.w + a1.w) + (a2.w + a3.w)) + ((a4.w + a5.w) + (a6.w + a7.w));
    return r;
}

__global__ __launch_bounds__(256) void reduce_pk_kernel() {
    int i = blockIdx.x * 256 + threadIdx.x;   // 0 .. W*H-1
    int lane = threadIdx.x & 31;
    int r = i & (H - 1);
    int w = i >> 9;

    float4 s = sum8(i);

    float n0 = __shfl_down_sync(0xffffffffu, s.x, 1);
    float n1 = __shfl_down_sync(0xffffffffu, s.y, 1);
    float n2 = __shfl_down_sync(0xffffffffu, s.z, 1);
    float n3 = __shfl_down_sync(0xffffffffu, s.w, 1);
    if (lane == 31) {
        int j = (i + 1 < W * H) ? i + 1 : i;
        float4 nn = sum8(j);
        n0 = nn.x; n1 = nn.y; n2 = nn.z; n3 = nn.w;
    }

    bool edge = (r == H - 1);
    float d0 = edge ? -s.x : n0 - s.x;
    float d1 = edge ? -s.y : n1 - s.y;
    float d2f = edge ? -s.z : n2 - s.z;
    float d3 = edge ? -s.w : n3 - s.w;

    __half2 v01 = __floats2half2_rn(s.x, s.y);
    __half2 v23 = __floats2half2_rn(s.z, s.w);
    __half2 e01 = __floats2half2_rn(d0, d1);
    __half2 e23 = __floats2half2_rn(d2f, d3);
    g_pkt[w * HP + 1 + r] = make_uint4(*(unsigned*)&v01, *(unsigned*)&v23,
                                       *(unsigned*)&e01, *(unsigned*)&e23);

    if (r == 0) {
        __half2 z2 = __floats2half2_rn(0.f, 0.f);
        unsigned zu = *(unsigned*)&z2;
        g_pkt[w * HP + 0] = make_uint4(zu, zu, *(unsigned*)&v01, *(unsigned*)&v23);
    }
    if (edge) {
        g_pkt[w * HP + H + 1] = make_uint4(0u, 0u, 0u, 0u);
    }
}

// ============================================================
// Backprojection: 32x32 tile, 4-way ANGLE SPLIT, 4 angles/barrier,
// half2 accumulation per quad, ONE fp32 flush per quad.
// Partials stored fp16-packed (uint2 per pixel).
// ============================================================
__device__ __forceinline__ void stage_group(int wbase, int tid, float X0f, float Y0f,
                                            const float4* scoef, float4* srb,
                                            uint4 (*sb)[WLEN], int w0) {
    int cnt = QW - wbase;
    if (cnt > 4) cnt = 4;
    if (cnt > 0 && tid < cnt * WLEN) {
        int a   = tid / WLEN;            // 0..3
        int idx = tid - a * WLEN;
        int wa  = wbase + a;
        float4 cf = scoef[wa];
        float pymin = fmaf(cf.x, X0f, fmaf(cf.y, Y0f, cf.z)) + cf.w;
        int lo = __float2int_rd(pymin) - 1;
        if (idx == 0)
            srb[wa & (NSTG - 1)] = make_float4(cf.x, cf.y, cf.z - (float)lo,
                                               cf.x * 8.0f);
        int g = lo + idx + 1;            // haloed table index
        unsigned ok = ((unsigned)g < (unsigned)HP) ? 16u : 0u;
        int gc = g < 0 ? 0 : (g > HP - 1 ? HP - 1 : g);
        const uint4* src = g_pkt + ((w0 + wa) * HP + gc);
        unsigned sa = (unsigned)__cvta_generic_to_shared(&sb[wa & (NSTG - 1)][idx]);
        asm volatile("cp.async.cg.shared.global [%0], [%1], 16, %2;\n"
                     :: "r"(sa), "l"(src), "r"(ok));
    }
    asm volatile("cp.async.commit_group;\n" ::: "memory");
}

// 4 angles, half2 accumulation, single fp32 flush
__device__ __forceinline__ void bp_quad(const float4* __restrict__ srb, int wl,
                                        const uint4* __restrict__ b0,
                                        const uint4* __restrict__ b1,
                                        const uint4* __restrict__ b2,
                                        const uint4* __restrict__ b3,
                                        float Xtf, float Ytf,
                                        float acc[4][4]) {
    float4 c0 = srb[(wl    ) & (NSTG - 1)];
    float4 c1 = srb[(wl + 1) & (NSTG - 1)];
    float4 c2 = srb[(wl + 2) & (NSTG - 1)];
    float4 c3 = srb[(wl + 3) & (NSTG - 1)];
    float py0 = fmaf(c0.x, Xtf, fmaf(c0.y, Ytf, c0.z));
    float py1 = fmaf(c1.x, Xtf, fmaf(c1.y, Ytf, c1.z));
    float py2 = fmaf(c2.x, Xtf, fmaf(c2.y, Ytf, c2.z));
    float py3 = fmaf(c3.x, Xtf, fmaf(c3.y, Ytf, c3.z));

    #pragma unroll
    for (int s = 0; s < 4; ++s) {
        int   ya = __float2int_rd(py0);
        float fa = py0 - (float)ya;
        uint4 qa = b0[ya];
        __half2 fa2 = __floats2half2_rn(fa, fa);
        __half2 p01 = __hfma2(u2h(qa.z), fa2, u2h(qa.x));
        __half2 p23 = __hfma2(u2h(qa.w), fa2, u2h(qa.y));

        int   yb = __float2int_rd(py1);
        float fb = py1 - (float)yb;
        uint4 qb = b1[yb];
        __half2 fb2 = __floats2half2_rn(fb, fb);
        p01 = __hadd2(p01, u2h(qb.x));
        p23 = __hadd2(p23, u2h(qb.y));
        p01 = __hfma2(u2h(qb.z), fb2, p01);
        p23 = __hfma2(u2h(qb.w), fb2, p23);

        int   yc = __float2int_rd(py2);
        float fc = py2 - (float)yc;
        uint4 qc = b2[yc];
        __half2 fc2 = __floats2half2_rn(fc, fc);
        p01 = __hadd2(p01, u2h(qc.x));
        p23 = __hadd2(p23, u2h(qc.y));
        p01 = __hfma2(u2h(qc.z), fc2, p01);
        p23 = __hfma2(u2h(qc.w), fc2, p23);

        int   yd = __float2int_rd(py3);
        float fd = py3 - (float)yd;
        uint4 qd = b3[yd];
        __half2 fd2 = __floats2half2_rn(fd, fd);
        p01 = __hadd2(p01, u2h(qd.x));
        p23 = __hadd2(p23, u2h(qd.y));
        p01 = __hfma2(u2h(qd.z), fd2, p01);
        p23 = __hfma2(u2h(qd.w), fd2, p23);

        float2 f01 = __half22float2(p01);
        float2 f23 = __half22float2(p23);
        acc[s][0] += f01.x;
        acc[s][1] += f01.y;
        acc[s][2] += f23.x;
        acc[s][3] += f23.y;
        py0 += c0.w;
        py1 += c1.w;
        py2 += c2.w;
        py3 += c3.w;
    }
}

// 2 angles (epilogue)
__device__ __forceinline__ void bp_pair(const float4* __restrict__ srb, int wl,
                                        const uint4* __restrict__ b0,
                                        const uint4* __restrict__ b1,
                                        float Xtf, float Ytf,
                                        float acc[4][4]) {
    float4 c0 = srb[wl & (NSTG - 1)];
    float4 c1 = srb[(wl + 1) & (NSTG - 1)];
    float py0 = fmaf(c0.x, Xtf, fmaf(c0.y, Ytf, c0.z));
    float py1 = fmaf(c1.x, Xtf, fmaf(c1.y, Ytf, c1.z));

    #pragma unroll
    for (int s = 0; s < 4; ++s) {
        int   ya = __float2int_rd(py0);
        float fa = py0 - (float)ya;
        uint4 qa = b0[ya];
        __half2 fa2 = __floats2half2_rn(fa, fa);
        __half2 p01 = __hfma2(u2h(qa.z), fa2, u2h(qa.x));
        __half2 p23 = __hfma2(u2h(qa.w), fa2, u2h(qa.y));

        int   yb = __float2int_rd(py1);
        float fb = py1 - (float)yb;
        uint4 qb = b1[yb];
        __half2 fb2 = __floats2half2_rn(fb, fb);
        p01 = __hadd2(p01, u2h(qb.x));
        p23 = __hadd2(p23, u2h(qb.y));
        p01 = __hfma2(u2h(qb.z), fb2, p01);
        p23 = __hfma2(u2h(qb.w), fb2, p23);

        float2 f01 = __half22float2(p01);
        float2 f23 = __half22float2(p23);
        acc[s][0] += f01.x;
        acc[s][1] += f01.y;
        acc[s][2] += f23.x;
        acc[s][3] += f23.y;
        py0 += c0.w;
        py1 += c1.w;
    }
}

__global__ __launch_bounds__(256) void backproj_kernel(const float* __restrict__ t_y) {
    __shared__ float4 scoef[QW];
    __shared__ float4 srb[NSTG];
    __shared__ uint4  sb[NSTG][WLEN];

    int tid  = threadIdx.x;
    int lane = tid & 31;
    int warp = tid >> 5;
    int lx = lane >> 2;       // 0..7
    int ly = lane & 3;        // 0..3

    int z  = blockIdx.z;
    int w0 = z * QW;

    if (tid < QW) {
        int w = w0 + tid;
        float cosv =  256.0f * __ldg(&t_y[w * DD + 256 * D + 257]);
        float sinv = -256.0f * __ldg(&t_y[w * DD + 257 * D + 256]);
        const float s = 255.5f / 256.0f;
        float A = -s * sinv;
        float B =  s * cosv;
        float C0 = 255.5f - 256.0f * B - 256.0f * A;
        float minAB = fminf(A * 31.0f, 0.0f) + fminf(B * 31.0f, 0.0f);
        scoef[tid] = make_float4(A, B, C0, minAB);
    }
    __syncthreads();

    int X0 = blockIdx.x * 32;
    int Y0 = blockIdx.y * 32;
    float X0f = (float)X0, Y0f = (float)Y0;

    int Xt = X0 + lx;                 // + s*8 per slot
    int Yt = Y0 + warp * 4 + ly;
    float Xtf = (float)Xt, Ytf = (float)Yt;

    float acc[4][4] = {};             // [slot][batch]

    // prologue: stage groups (0-3), (4-7)
    stage_group(0, tid, X0f, Y0f, scoef, srb, sb, w0);
    stage_group(4, tid, X0f, Y0f, scoef, srb, sb, w0);

    // main loop: 22 iterations x 4 angles (covers 0..87)
    for (int wl = 0; wl < 88; wl += 4) {
        asm volatile("cp.async.wait_group 1;\n" ::: "memory");
        __syncthreads();

        stage_group(wl + 8, tid, X0f, Y0f, scoef, srb, sb, w0);

        bp_quad(srb, wl,
                sb[(wl    ) & (NSTG - 1)], sb[(wl + 1) & (NSTG - 1)],
                sb[(wl + 2) & (NSTG - 1)], sb[(wl + 3) & (NSTG - 1)],
                Xtf, Ytf, acc);
    }

    // epilogue: angles 88, 89
    asm volatile("cp.async.wait_group 0;\n" ::: "memory");
    __syncthreads();
    bp_pair(srb, 88, sb[88 & (NSTG - 1)], sb[89 & (NSTG - 1)], Xtf, Ytf, acc);

    uint2* pout = g_parth[z];
    #pragma unroll
    for (int s = 0; s < 4; ++s) {
        int X = Xt + s * 8;
        int o = X * D + Yt;
        __half2 h01 = __floats2half2_rn(acc[s][0], acc[s][1]);
        __half2 h23 = __floats2half2_rn(acc[s][2], acc[s][3]);
        pout[o] = make_uint2(*(unsigned*)&h01, *(unsigned*)&h23);
    }
}

// ============================================================
// Combine: 4 pixels/thread, vectorized loads (uint4) and
// float4 plane writes. out[n*DD+i] = (sum_z parth[z][i].n)*scale
// ============================================================
__global__ __launch_bounds__(256) void combine_kernel(float* __restrict__ out) {
    const float scale = 0.004363323129985824f;  // pi / 720
    int i = (blockIdx.x * 256 + threadIdx.x) * 4;   // base pixel index
    float a[4][4] = {};                             // [pixel][batch]

    #pragma unroll
    for (int z = 0; z < 4; ++z) {
        const uint4* p = (const uint4*)(g_parth[z] + i);
        uint4 qa = p[0];   // pixels i, i+1
        uint4 qb = p[1];   // pixels i+2, i+3
        float2 f;
        f = __half22float2(u2h(qa.x)); a[0][0] += f.x; a[0][1] += f.y;
        f = __half22float2(u2h(qa.y)); a[0][2] += f.x; a[0][3] += f.y;
        f = __half22float2(u2h(qa.z)); a[1][0] += f.x; a[1][1] += f.y;
        f = __half22float2(u2h(qa.w)); a[1][2] += f.x; a[1][3] += f.y;
        f = __half22float2(u2h(qb.x)); a[2][0] += f.x; a[2][1] += f.y;
        f = __half22float2(u2h(qb.y)); a[2][2] += f.x; a[2][3] += f.y;
        f = __half22float2(u2h(qb.z)); a[3][0] += f.x; a[3][1] += f.y;
        f = __half22float2(u2h(qb.w)); a[3][2] += f.x; a[3][3] += f.y;
    }

    #pragma unroll
    for (int n = 0; n < NB; ++n) {
        float4 r;
        r.x = a[0][n] * scale;
        r.y = a[1][n] * scale;
        r.z = a[2][n] * scale;
        r.w = a[3][n] * scale;
        *(float4*)(out + n * DD + i) = r;
    }
}

extern "C" void kernel_launch(void* const* d_in, const int* in_sizes, int n_in,
                              void* d_out, int out_size) {
    const float* radon = (const float*)d_in[0];
    const float* hG    = (const float*)d_in[1];
    const float* t_y   = (const float*)d_in[2];
    float* out = (float*)d_out;

    filter_kernel<<<dim3(8, 23, KSL), 256>>>(radon, hG);
    reduce_pk_kernel<<<(W * H) / 256, 256>>>();
    backproj_kernel<<<dim3(16, 16, 4), 256>>>(t_y);
    combine_kernel<<<DD / 4 / 256, 256>>>(out);
}